// round 14
// baseline (speedup 1.0000x reference)
#include <cuda_runtime.h>

// Shapes (fixed by the problem)
#define BB   4
#define LL   2048
#define DD   1024
#define VV   32
#define KK   4096
#define NTOK (BB*LL)     // 8192 tokens
#define TPB  32          // tokens per block (= warp lanes; lane t owns token t)
#define NW   8           // warps per block (each owns a K-slice)
#define KW   (KK/NW)     // 512 codes per warp
#define CT   16          // codes per smem tile
#define NT2  (KW/CT)     // 32 tiles per warp

// Scratch (static device globals — no allocation)
__device__ float g_embn[KK*VV];    // normalized codebook
__device__ float g_ne2[KK];        // sum(emb_n^2) + 1 per code (softmax shift folded)
__device__ float g_wpiT[VV*DD];    // Wpi transposed: [v][d]
__device__ float g_wpT4[DD*VV];    // Wp interleaved: [(d/4)][v][d%4] -> coalesced float4

typedef unsigned long long ull;

__device__ __forceinline__ ull fma2(ull a, ull b, ull c){
    ull d;
    asm("fma.rn.f32x2 %0, %1, %2, %3;" : "=l"(d) : "l"(a), "l"(b), "l"(c));
    return d;
}
__device__ __forceinline__ ull add2(ull a, ull b){
    ull d;
    asm("add.rn.f32x2 %0, %1, %2;" : "=l"(d) : "l"(a), "l"(b));
    return d;
}
__device__ __forceinline__ ull pack2(float x, float y){
    ull r;
    asm("mov.b64 %0, {%1, %2};" : "=l"(r) : "f"(x), "f"(y));
    return r;
}
__device__ __forceinline__ float2 unpack2(ull a){
    float x, y;
    asm("mov.b64 {%0, %1}, %2;" : "=f"(x), "=f"(y) : "l"(a));
    return make_float2(x, y);
}
__device__ __forceinline__ void cp16(void* dst, const void* src){
    unsigned s = (unsigned)__cvta_generic_to_shared(dst);
    asm volatile("cp.async.cg.shared.global [%0], [%1], 16;" :: "r"(s), "l"(src));
}
__device__ __forceinline__ void cp4(void* dst, const void* src){
    unsigned s = (unsigned)__cvta_generic_to_shared(dst);
    asm volatile("cp.async.ca.shared.global [%0], [%1], 4;" :: "r"(s), "l"(src));
}

// ---------------------------------------------------------------------------
// Merged prep kernel (unchanged)
// ---------------------------------------------------------------------------
__global__ void prep_kernel(const float* __restrict__ emb,
                            const float* __restrict__ Wpi,
                            const float* __restrict__ Wp,
                            float* __restrict__ out, long long out_size){
    int b = blockIdx.x;
    if(b < 512){
        int r = b * 8 + (threadIdx.x >> 5);
        int v = threadIdx.x & 31;
        float val = emb[r*VV + v];
        float ss = val * val;
        #pragma unroll
        for(int o=16;o;o>>=1) ss += __shfl_xor_sync(0xffffffffu, ss, o);
        float en = val * rsqrtf(ss);
        g_embn[r*VV + v] = en;
        float s2 = en * en;
        #pragma unroll
        for(int o=16;o;o>>=1) s2 += __shfl_xor_sync(0xffffffffu, s2, o);
        if(v == 0) g_ne2[r] = s2 + 1.0f;   // +1: fixed softmax shift folded in
    } else if(b < 640){
        int i = (b - 512) * 256 + threadIdx.x;   // over D*V
        int d = i >> 5, v = i & 31;              // Wpi[d][v]
        g_wpiT[v*DD + d] = Wpi[i];
        if(i == 0){
            long long qn = (long long)NTOK * DD;
            if(out_size >= qn + NTOK + 1) out[qn + NTOK] = 0.0f;  // vq_loss
        }
    } else {
        int i = (b - 640) * 256 + threadIdx.x;   // over V*D (coalesced Wp read)
        int v = i >> 10, d = i & 1023;           // Wp[v][d]
        g_wpT4[(d >> 2)*128 + v*4 + (d & 3)] = Wp[i];
    }
}

// ---------------------------------------------------------------------------
// Main fused kernel: token-major lanes (R9 layout), K-sliced warps,
// two-phase inner loop: score-all-codes (stage p in regs) then accumulate
// ---------------------------------------------------------------------------
__global__ void __launch_bounds__(256, 2)
vq_main_kernel(const float* __restrict__ h,
               const float* __restrict__ attn_mask,
               const float* __restrict__ bp,
               const float* __restrict__ bpi,
               float* __restrict__ out, long long out_size)
{
    // tiles: warp w, buf b at offset ((w*2+b)*CT)*VV floats; 16 KB total for tiles,
    // array sized 9216 floats (36 KB) because it is reused as 256x36 partial rows.
    __shared__ __align__(16) float s_e[9216];           // 36 KB
    __shared__ __align__(16) float s_ne2[NW][2][CT];    // 1 KB
    __shared__ __align__(16) float s_hp[TPB*36];        // 4.6 KB (padded rows)
    __shared__ __align__(16) float4 s_comb[NW*TPB];     // 16 KB.. no: 256*16B = 4 KB
    __shared__ __align__(16) float s_scale[TPB];
    __shared__ __align__(16) float s_q[TPB*VV];         // 4 KB

    const int tid  = threadIdx.x;
    const int w    = tid >> 5;        // 0..7 : K-slice id
    const int lane = tid & 31;        // token id within block
    const int blk  = blockIdx.x;
    const long long qn = (long long)NTOK * DD;

    // ---- prefetch this warp's tile 0 (overlaps phase 1) ----
    {
        const float* src = g_embn + (w*KW)*VV;
        float* dst = s_e + (w*2 + 0)*CT*VV;
        #pragma unroll
        for(int r=0;r<4;r++){
            int i = lane + 32*r;      // 128 x 16B chunks = 2KB
            cp16(dst + i*4, src + i*4);
        }
        if(lane < CT) cp4(&s_ne2[w][0][lane], g_ne2 + w*KW + lane);
        asm volatile("cp.async.commit_group;");
    }

    // ---- phase 1: hp for 4 tokens per warp (lane = v index) ----
    {
        const int tok0 = blk*TPB + 4*w;
        const float4* h0 = (const float4*)(h + (long long)(tok0  )*DD);
        const float4* h1 = (const float4*)(h + (long long)(tok0+1)*DD);
        const float4* h2 = (const float4*)(h + (long long)(tok0+2)*DD);
        const float4* h3 = (const float4*)(h + (long long)(tok0+3)*DD);
        const float4* wT = (const float4*)g_wpT4;
        float bpl = __ldg(bp + lane);
        float d0=bpl, d1=bpl, d2=bpl, d3=bpl;
        #pragma unroll 4
        for(int g=0;g<DD/4;g++){
            float4 wv = __ldg(wT + g*32 + lane);   // lane-consecutive
            float4 a  = __ldg(h0 + g);
            d0 += wv.x*a.x + wv.y*a.y + wv.z*a.z + wv.w*a.w;
            float4 b  = __ldg(h1 + g);
            d1 += wv.x*b.x + wv.y*b.y + wv.z*b.z + wv.w*b.w;
            float4 c  = __ldg(h2 + g);
            d2 += wv.x*c.x + wv.y*c.y + wv.z*c.z + wv.w*c.w;
            float4 e  = __ldg(h3 + g);
            d3 += wv.x*e.x + wv.y*e.y + wv.z*e.z + wv.w*e.w;
        }
        float s0=d0*d0, s1=d1*d1, s2=d2*d2, s3=d3*d3;
        #pragma unroll
        for(int o=16;o;o>>=1){
            s0 += __shfl_xor_sync(0xffffffffu, s0, o);
            s1 += __shfl_xor_sync(0xffffffffu, s1, o);
            s2 += __shfl_xor_sync(0xffffffffu, s2, o);
            s3 += __shfl_xor_sync(0xffffffffu, s3, o);
        }
        s_hp[(4*w  )*36 + lane] = d0 * (2.0f * rsqrtf(s0));  // 2*normalized hp
        s_hp[(4*w+1)*36 + lane] = d1 * (2.0f * rsqrtf(s1));
        s_hp[(4*w+2)*36 + lane] = d2 * (2.0f * rsqrtf(s2));
        s_hp[(4*w+3)*36 + lane] = d3 * (2.0f * rsqrtf(s3));
    }
    __syncthreads();

    // ---- each lane loads ITS token's hp into registers ----
    ull hp[16];
    {
        const ulonglong2* hr = (const ulonglong2*)&s_hp[lane*36];  // 144B rows, 16B aligned
        #pragma unroll
        for(int u=0;u<8;u++){ ulonglong2 x = hr[u]; hp[2*u] = x.x; hp[2*u+1] = x.y; }
    }

    // ---- main loop over this warp's K-slice (warp-private pipeline) ----
    ull acc[16];
    #pragma unroll
    for(int u=0;u<16;u++) acc[u] = 0ull;
    float l = 0.f, best = -1e30f;
    int   idx = 0;
    const int cbase = w*KW;

    for(int t2=0;t2<NT2;t2++){
        const int buf = t2 & 1;
        if(t2 + 1 < NT2){
            const float* src = g_embn + (cbase + (t2+1)*CT)*VV;
            float* dst = s_e + (w*2 + (buf^1))*CT*VV;
            #pragma unroll
            for(int r=0;r<4;r++){
                int i = lane + 32*r;
                cp16(dst + i*4, src + i*4);
            }
            if(lane < CT) cp4(&s_ne2[w][buf^1][lane], g_ne2 + cbase + (t2+1)*CT + lane);
            asm volatile("cp.async.commit_group;");
            asm volatile("cp.async.wait_group 1;");
        } else {
            asm volatile("cp.async.wait_group 0;");
        }
        __syncwarp();

        const float* se = s_e + (w*2 + buf)*CT*VV;
        const int codebase = cbase + t2*CT;
        float pv[CT];

        // ---- phase A: scores for all CT codes (independent chains, deep ILP) ----
        #pragma unroll
        for(int j=0;j<CT;j++){
            const ulonglong2* er = (const ulonglong2*)(se + j*VV);  // broadcast
            ull e[16];
            #pragma unroll
            for(int u=0;u<8;u++){ ulonglong2 x = er[u]; e[2*u] = x.x; e[2*u+1] = x.y; }
            ull p0=0ull, p1=0ull, p2=0ull, p3=0ull;
            #pragma unroll
            for(int u=0;u<4;u++){
                p0 = fma2(hp[u   ], e[u   ], p0);
                p1 = fma2(hp[4+u ], e[4+u ], p1);
                p2 = fma2(hp[8+u ], e[8+u ], p2);
                p3 = fma2(hp[12+u], e[12+u], p3);
            }
            ull s01 = add2(p0, p1), s23 = add2(p2, p3);
            float2 f = unpack2(add2(s01, s23));
            float sc = (f.x + f.y) - s_ne2[w][buf][j];   // = 2*s - ne2 - 1 (shifted)
            if(sc > best){ best = sc; idx = codebase + j; }
            float p = __expf(sc);                        // shifted score <= ~3e-4
            pv[j] = p;
            l += p;
        }

        // ---- phase B: accumulate (LDS feeds fma2 directly; no expf in chain) ----
        #pragma unroll
        for(int j=0;j<CT;j++){
            const ulonglong2* er = (const ulonglong2*)(se + j*VV);
            ull pp = pack2(pv[j], pv[j]);
            #pragma unroll
            for(int u=0;u<8;u++){
                ulonglong2 x = er[u];
                acc[2*u  ] = fma2(pp, x.x, acc[2*u  ]);
                acc[2*u+1] = fma2(pp, x.y, acc[2*u+1]);
            }
        }
    }

    // ---- write per-warp partials (overlay s_e; all warps done reading) ----
    __syncthreads();
    {
        float* prow = s_e + (w*TPB + lane)*36;   // padded rows, 256 x 36 floats
        ulonglong2* pr2 = (ulonglong2*)prow;
        #pragma unroll
        for(int u=0;u<8;u++){ ulonglong2 x; x.x = acc[2*u]; x.y = acc[2*u+1]; pr2[u] = x; }
        s_comb[w*TPB + lane] = make_float4(l, best, __int_as_float(idx), 0.f);
    }
    __syncthreads();

    // ---- cross-warp combine: 8 threads per token ----
    {
        const int t = tid >> 3, g = tid & 7;
        float4 sum = make_float4(0.f,0.f,0.f,0.f);
        #pragma unroll
        for(int ww=0;ww<NW;ww++){
            const float4* pr = (const float4*)(s_e + (ww*TPB + t)*36);
            float4 v = pr[g];
            sum.x += v.x; sum.y += v.y; sum.z += v.z; sum.w += v.w;
        }
        if(g == 0){
            float lt = 0.f, bv = -1e30f; int bi = 0;
            #pragma unroll
            for(int ww=0;ww<NW;ww++){
                float4 c = s_comb[ww*TPB + t];
                lt += c.x;
                if(c.y > bv){ bv = c.y; bi = __float_as_int(c.z); }   // ascending slices: first max kept
            }
            float mk = (attn_mask[blk*TPB + t] == 1.0f) ? 1.0f : 0.0f;
            s_scale[t] = mk / lt;
            if(out_size >= qn + NTOK) out[qn + blk*TPB + t] = mk * (float)bi;
        }
        __syncthreads();
        float scl = s_scale[t];
        ((float4*)(s_q + t*VV))[g] = make_float4(sum.x*scl, sum.y*scl, sum.z*scl, sum.w*scl);
    }
    __syncthreads();

    // ---- epilogue: out = q @ Wpi^T + bpi; warp w -> tokens 4w..4w+3, 2 passes ----
    #pragma unroll 1
    for(int ps=0; ps<2; ps++){
        const int tA = 4*w + 2*ps, tB = tA + 1;
        float4 oA[8], oB[8];
        #pragma unroll
        for(int m=0;m<8;m++){ oA[m] = make_float4(0,0,0,0); oB[m] = make_float4(0,0,0,0); }
        #pragma unroll 2
        for(int v=0;v<VV;v++){
            float qa = s_q[tA*VV + v];      // smem broadcast
            float qb = s_q[tB*VV + v];
            const float4* wr = (const float4*)(g_wpiT + v*DD);
            #pragma unroll
            for(int m=0;m<8;m++){
                float4 wv = __ldg(wr + m*32 + lane);   // d = 128*m + 4*lane, coalesced (L2-hot)
                oA[m].x += qa*wv.x; oA[m].y += qa*wv.y; oA[m].z += qa*wv.z; oA[m].w += qa*wv.w;
                oB[m].x += qb*wv.x; oB[m].y += qb*wv.y; oB[m].z += qb*wv.z; oB[m].w += qb*wv.w;
            }
        }
        float4* outA = (float4*)(out + (long long)(blk*TPB + tA) * DD);
        float4* outB = (float4*)(out + (long long)(blk*TPB + tB) * DD);
        const float4* bp4 = (const float4*)bpi;
        #pragma unroll
        for(int m=0;m<8;m++){
            float4 bv = __ldg(bp4 + m*32 + lane);
            float4 a = oA[m]; a.x += bv.x; a.y += bv.y; a.z += bv.z; a.w += bv.w;
            float4 b = oB[m]; b.x += bv.x; b.y += bv.y; b.z += bv.z; b.w += bv.w;
            outA[m*32 + lane] = a;
            outB[m*32 + lane] = b;
        }
    }
}

extern "C" void kernel_launch(void* const* d_in, const int* in_sizes, int n_in,
                              void* d_out, int out_size)
{
    const float* h    = (const float*)d_in[0];   // [B,L,D]
    const float* mask = (const float*)d_in[1];   // [B,L]
    const float* Wp   = (const float*)d_in[2];   // [V,D]
    const float* bp   = (const float*)d_in[3];   // [V]
    const float* Wpi  = (const float*)d_in[4];   // [D,V]
    const float* bpi  = (const float*)d_in[5];   // [D]
    const float* emb  = (const float*)d_in[6];   // [K,V]
    float* out = (float*)d_out;
    long long osz = (long long)out_size;

    prep_kernel<<<768, 256>>>(emb, Wpi, Wp, out, osz);
    vq_main_kernel<<<NTOK/TPB, 256>>>(h, mask, bp, bpi, out, osz);
}

// round 15
// speedup vs baseline: 3.9409x; 3.9409x over previous
#include <cuda_runtime.h>

// Shapes (fixed by the problem)
#define BB   4
#define LL   2048
#define DD   1024
#define VV   32
#define KK   4096
#define NTOK (BB*LL)     // 8192 tokens
#define TPB  32          // tokens per block (= warp lanes; lane t owns token t)
#define NW   8           // warps per block (each owns a K-slice)
#define KW   (KK/NW)     // 512 codes per warp
#define CT   32          // codes per smem tile
#define NT2  (KW/CT)     // 16 tiles per warp

// Scratch (static device globals — no allocation)
__device__ float g_embn[KK*VV];    // normalized codebook
__device__ float g_ne2[KK];        // sum(emb_n^2) + 1 per code (softmax shift folded)
__device__ float g_wpiT[VV*DD];    // Wpi transposed: [v][d]
__device__ float g_wpT4[DD*VV];    // Wp interleaved: [(d/4)][v][d%4] -> coalesced float4

typedef unsigned long long ull;

__device__ __forceinline__ ull fma2(ull a, ull b, ull c){
    ull d;
    asm("fma.rn.f32x2 %0, %1, %2, %3;" : "=l"(d) : "l"(a), "l"(b), "l"(c));
    return d;
}
__device__ __forceinline__ ull add2(ull a, ull b){
    ull d;
    asm("add.rn.f32x2 %0, %1, %2;" : "=l"(d) : "l"(a), "l"(b));
    return d;
}
__device__ __forceinline__ ull pack2(float x, float y){
    ull r;
    asm("mov.b64 %0, {%1, %2};" : "=l"(r) : "f"(x), "f"(y));
    return r;
}
__device__ __forceinline__ float2 unpack2(ull a){
    float x, y;
    asm("mov.b64 {%0, %1}, %2;" : "=f"(x), "=f"(y) : "l"(a));
    return make_float2(x, y);
}
// volatile 16B shared load at a shared-space address — issued at use site,
// cannot be CSE'd into long-lived registers (spill protection)
__device__ __forceinline__ ulonglong2 lds128s(unsigned addr){
    ulonglong2 r;
    asm volatile("ld.shared.v2.u64 {%0, %1}, [%2];" : "=l"(r.x), "=l"(r.y) : "r"(addr));
    return r;
}
__device__ __forceinline__ void cp16(void* dst, const void* src){
    unsigned s = (unsigned)__cvta_generic_to_shared(dst);
    asm volatile("cp.async.cg.shared.global [%0], [%1], 16;" :: "r"(s), "l"(src));
}
__device__ __forceinline__ void cp4(void* dst, const void* src){
    unsigned s = (unsigned)__cvta_generic_to_shared(dst);
    asm volatile("cp.async.ca.shared.global [%0], [%1], 4;" :: "r"(s), "l"(src));
}

// ---------------------------------------------------------------------------
// Merged prep kernel (unchanged)
// ---------------------------------------------------------------------------
__global__ void prep_kernel(const float* __restrict__ emb,
                            const float* __restrict__ Wpi,
                            const float* __restrict__ Wp,
                            float* __restrict__ out, long long out_size){
    int b = blockIdx.x;
    if(b < 512){
        int r = b * 8 + (threadIdx.x >> 5);
        int v = threadIdx.x & 31;
        float val = emb[r*VV + v];
        float ss = val * val;
        #pragma unroll
        for(int o=16;o;o>>=1) ss += __shfl_xor_sync(0xffffffffu, ss, o);
        float en = val * rsqrtf(ss);
        g_embn[r*VV + v] = en;
        float s2 = en * en;
        #pragma unroll
        for(int o=16;o;o>>=1) s2 += __shfl_xor_sync(0xffffffffu, s2, o);
        if(v == 0) g_ne2[r] = s2 + 1.0f;   // +1: fixed softmax shift folded in
    } else if(b < 640){
        int i = (b - 512) * 256 + threadIdx.x;   // over D*V
        int d = i >> 5, v = i & 31;              // Wpi[d][v]
        g_wpiT[v*DD + d] = Wpi[i];
        if(i == 0){
            long long qn = (long long)NTOK * DD;
            if(out_size >= qn + NTOK + 1) out[qn + NTOK] = 0.0f;  // vq_loss
        }
    } else {
        int i = (b - 640) * 256 + threadIdx.x;   // over V*D (coalesced Wp read)
        int v = i >> 10, d = i & 1023;           // Wp[v][d]
        g_wpT4[(d >> 2)*128 + v*4 + (d & 3)] = Wp[i];
    }
}

// ---------------------------------------------------------------------------
// Main fused kernel: token-major lanes (R9 layout), K-sliced warps,
// 1-deep software pipeline: score code j while accumulating code j-1
// ---------------------------------------------------------------------------
__global__ void __launch_bounds__(256, 2)
vq_main_kernel(const float* __restrict__ h,
               const float* __restrict__ attn_mask,
               const float* __restrict__ bp,
               const float* __restrict__ bpi,
               float* __restrict__ out, long long out_size)
{
    __shared__ __align__(16) float s_e[NW][2][CT*VV];   // 64 KB (reused for partials)
    __shared__ __align__(16) float s_ne2[NW][2][CT];    // 2 KB
    __shared__ __align__(16) float s_hp[TPB*36];        // 4.6 KB (padded rows)
    __shared__ __align__(16) float4 s_comb[NW*TPB];     // 4 KB {l, best, idx, -}
    __shared__ __align__(16) float s_scale[TPB];
    __shared__ __align__(16) float s_q[TPB*VV];         // 4 KB

    const int tid  = threadIdx.x;
    const int w    = tid >> 5;        // 0..7 : K-slice id
    const int lane = tid & 31;        // token id within block
    const int blk  = blockIdx.x;
    const long long qn = (long long)NTOK * DD;

    // ---- prefetch this warp's tile 0 (overlaps phase 1) ----
    {
        const float* src = g_embn + (w*KW)*VV;
        #pragma unroll
        for(int r=0;r<8;r++){
            int i = lane + 32*r;      // 256 x 16B chunks = 4KB
            cp16(&s_e[w][0][i*4], src + i*4);
        }
        cp4(&s_ne2[w][0][lane], g_ne2 + w*KW + lane);
        asm volatile("cp.async.commit_group;");
    }

    // ---- phase 1: hp for 4 tokens per warp (lane = v index) ----
    {
        const int tok0 = blk*TPB + 4*w;
        const float4* h0 = (const float4*)(h + (long long)(tok0  )*DD);
        const float4* h1 = (const float4*)(h + (long long)(tok0+1)*DD);
        const float4* h2 = (const float4*)(h + (long long)(tok0+2)*DD);
        const float4* h3 = (const float4*)(h + (long long)(tok0+3)*DD);
        const float4* wT = (const float4*)g_wpT4;
        float bpl = __ldg(bp + lane);
        float d0=bpl, d1=bpl, d2=bpl, d3=bpl;
        #pragma unroll 4
        for(int g=0;g<DD/4;g++){
            float4 wv = __ldg(wT + g*32 + lane);   // lane-consecutive
            float4 a  = __ldg(h0 + g);
            d0 += wv.x*a.x + wv.y*a.y + wv.z*a.z + wv.w*a.w;
            float4 b  = __ldg(h1 + g);
            d1 += wv.x*b.x + wv.y*b.y + wv.z*b.z + wv.w*b.w;
            float4 c  = __ldg(h2 + g);
            d2 += wv.x*c.x + wv.y*c.y + wv.z*c.z + wv.w*c.w;
            float4 e  = __ldg(h3 + g);
            d3 += wv.x*e.x + wv.y*e.y + wv.z*e.z + wv.w*e.w;
        }
        float s0=d0*d0, s1=d1*d1, s2=d2*d2, s3=d3*d3;
        #pragma unroll
        for(int o=16;o;o>>=1){
            s0 += __shfl_xor_sync(0xffffffffu, s0, o);
            s1 += __shfl_xor_sync(0xffffffffu, s1, o);
            s2 += __shfl_xor_sync(0xffffffffu, s2, o);
            s3 += __shfl_xor_sync(0xffffffffu, s3, o);
        }
        s_hp[(4*w  )*36 + lane] = d0 * (2.0f * rsqrtf(s0));  // 2*normalized hp
        s_hp[(4*w+1)*36 + lane] = d1 * (2.0f * rsqrtf(s1));
        s_hp[(4*w+2)*36 + lane] = d2 * (2.0f * rsqrtf(s2));
        s_hp[(4*w+3)*36 + lane] = d3 * (2.0f * rsqrtf(s3));
    }
    __syncthreads();

    // ---- each lane loads ITS token's hp into registers ----
    ull hp[16];
    {
        const ulonglong2* hr = (const ulonglong2*)&s_hp[lane*36];  // 144B rows, 16B aligned
        #pragma unroll
        for(int u=0;u<8;u++){ ulonglong2 x = hr[u]; hp[2*u] = x.x; hp[2*u+1] = x.y; }
    }

    // ---- main loop over this warp's K-slice (warp-private pipeline) ----
    ull acc[16];
    #pragma unroll
    for(int u=0;u<16;u++) acc[u] = 0ull;
    float l = 0.f, best = -1e30f;
    int   idx = 0;
    const int cbase = w*KW;

    float    p_prev   = 0.f;    // staged softmax weight of previous code
    unsigned row_prev = 0u;     // shared-space address of previous code's row

    for(int t2=0;t2<NT2;t2++){
        const int buf = t2 & 1;

        // drain the pending last code of the PREVIOUS tile before its buffer
        // is overwritten by the cp.async issued below (t2=0: nothing pending)
        if(t2){
            ull pp = pack2(p_prev, p_prev);
            #pragma unroll
            for(int u=0;u<8;u++){
                ulonglong2 x = lds128s(row_prev + u*16);
                acc[2*u  ] = fma2(pp, x.x, acc[2*u  ]);
                acc[2*u+1] = fma2(pp, x.y, acc[2*u+1]);
            }
        }

        if(t2 + 1 < NT2){
            const float* src = g_embn + (cbase + (t2+1)*CT)*VV;
            #pragma unroll
            for(int r=0;r<8;r++){
                int i = lane + 32*r;
                cp16(&s_e[w][buf^1][i*4], src + i*4);
            }
            cp4(&s_ne2[w][buf^1][lane], g_ne2 + cbase + (t2+1)*CT + lane);
            asm volatile("cp.async.commit_group;");
            asm volatile("cp.async.wait_group 1;");
        } else {
            asm volatile("cp.async.wait_group 0;");
        }
        __syncwarp();

        const float* se = &s_e[w][buf][0];
        const unsigned se_base = (unsigned)__cvta_generic_to_shared(se);
        const int codebase = cbase + t2*CT;

        // ---- j = 0: score only (pipeline fill) ----
        {
            const ulonglong2* er = (const ulonglong2*)se;
            ull e[16];
            #pragma unroll
            for(int u=0;u<8;u++){ ulonglong2 x = er[u]; e[2*u] = x.x; e[2*u+1] = x.y; }
            ull c0=0ull, c1=0ull, c2=0ull, c3=0ull;
            #pragma unroll
            for(int u=0;u<4;u++){
                c0 = fma2(hp[u   ], e[u   ], c0);
                c1 = fma2(hp[4+u ], e[4+u ], c1);
                c2 = fma2(hp[8+u ], e[8+u ], c2);
                c3 = fma2(hp[12+u], e[12+u], c3);
            }
            float2 f = unpack2(add2(add2(c0, c1), add2(c2, c3)));
            float sc = (f.x + f.y) - s_ne2[w][buf][0];   // = 2*s - ne2 - 1
            if(sc > best){ best = sc; idx = codebase; }
            float p = __expf(sc);
            l += p;
            p_prev = p; row_prev = se_base;
        }

        // ---- j = 1..CT-1: score code j, accumulate code j-1 (independent) ----
        #pragma unroll 1
        for(int j=1;j<CT;j++){
            const ulonglong2* er = (const ulonglong2*)(se + j*VV);
            ull e[16];
            #pragma unroll
            for(int u=0;u<8;u++){ ulonglong2 x = er[u]; e[2*u] = x.x; e[2*u+1] = x.y; }
            ull c0=0ull, c1=0ull, c2=0ull, c3=0ull;
            #pragma unroll
            for(int u=0;u<4;u++){
                c0 = fma2(hp[u   ], e[u   ], c0);
                c1 = fma2(hp[4+u ], e[4+u ], c1);
                c2 = fma2(hp[8+u ], e[8+u ], c2);
                c3 = fma2(hp[12+u], e[12+u], c3);
            }
            // drain code j-1 while the score chain above resolves
            {
                ull pp = pack2(p_prev, p_prev);
                #pragma unroll
                for(int u=0;u<8;u++){
                    ulonglong2 x = lds128s(row_prev + u*16);
                    acc[2*u  ] = fma2(pp, x.x, acc[2*u  ]);
                    acc[2*u+1] = fma2(pp, x.y, acc[2*u+1]);
                }
            }
            float2 f = unpack2(add2(add2(c0, c1), add2(c2, c3)));
            float sc = (f.x + f.y) - s_ne2[w][buf][j];   // = 2*s - ne2 - 1
            if(sc > best){ best = sc; idx = codebase + j; }
            float p = __expf(sc);                        // shifted score <= ~3e-4
            l += p;
            p_prev = p; row_prev = se_base + j*(VV*4);
        }
    }

    // ---- final drain (last code of last tile) ----
    {
        ull pp = pack2(p_prev, p_prev);
        #pragma unroll
        for(int u=0;u<8;u++){
            ulonglong2 x = lds128s(row_prev + u*16);
            acc[2*u  ] = fma2(pp, x.x, acc[2*u  ]);
            acc[2*u+1] = fma2(pp, x.y, acc[2*u+1]);
        }
    }

    // ---- write per-warp partials (overlay s_e; all warps done reading) ----
    __syncthreads();
    {
        float* prow = ((float*)s_e) + (w*TPB + lane)*36;   // padded rows
        ulonglong2* pr2 = (ulonglong2*)prow;
        #pragma unroll
        for(int u=0;u<8;u++){ ulonglong2 x; x.x = acc[2*u]; x.y = acc[2*u+1]; pr2[u] = x; }
        s_comb[w*TPB + lane] = make_float4(l, best, __int_as_float(idx), 0.f);
    }
    __syncthreads();

    // ---- cross-warp combine: 8 threads per token ----
    {
        const int t = tid >> 3, g = tid & 7;
        float4 sum = make_float4(0.f,0.f,0.f,0.f);
        #pragma unroll
        for(int ww=0;ww<NW;ww++){
            const float4* pr = (const float4*)(((float*)s_e) + (ww*TPB + t)*36);
            float4 v = pr[g];
            sum.x += v.x; sum.y += v.y; sum.z += v.z; sum.w += v.w;
        }
        if(g == 0){
            float lt = 0.f, bv = -1e30f; int bi = 0;
            #pragma unroll
            for(int ww=0;ww<NW;ww++){
                float4 c = s_comb[ww*TPB + t];
                lt += c.x;
                if(c.y > bv){ bv = c.y; bi = __float_as_int(c.z); }   // ascending slices: first max kept
            }
            float mk = (attn_mask[blk*TPB + t] == 1.0f) ? 1.0f : 0.0f;
            s_scale[t] = mk / lt;
            if(out_size >= qn + NTOK) out[qn + blk*TPB + t] = mk * (float)bi;
        }
        __syncthreads();
        float scl = s_scale[t];
        ((float4*)(s_q + t*VV))[g] = make_float4(sum.x*scl, sum.y*scl, sum.z*scl, sum.w*scl);
    }
    __syncthreads();

    // ---- epilogue: out = q @ Wpi^T + bpi; warp w -> tokens 4w..4w+3, 2 passes ----
    #pragma unroll 1
    for(int ps=0; ps<2; ps++){
        const int tA = 4*w + 2*ps, tB = tA + 1;
        float4 oA[8], oB[8];
        #pragma unroll
        for(int m=0;m<8;m++){ oA[m] = make_float4(0,0,0,0); oB[m] = make_float4(0,0,0,0); }
        #pragma unroll 2
        for(int v=0;v<VV;v++){
            float qa = s_q[tA*VV + v];      // smem broadcast
            float qb = s_q[tB*VV + v];
            const float4* wr = (const float4*)(g_wpiT + v*DD);
            #pragma unroll
            for(int m=0;m<8;m++){
                float4 wv = __ldg(wr + m*32 + lane);   // d = 128*m + 4*lane, coalesced (L2-hot)
                oA[m].x += qa*wv.x; oA[m].y += qa*wv.y; oA[m].z += qa*wv.z; oA[m].w += qa*wv.w;
                oB[m].x += qb*wv.x; oB[m].y += qb*wv.y; oB[m].z += qb*wv.z; oB[m].w += qb*wv.w;
            }
        }
        float4* outA = (float4*)(out + (long long)(blk*TPB + tA) * DD);
        float4* outB = (float4*)(out + (long long)(blk*TPB + tB) * DD);
        const float4* bp4 = (const float4*)bpi;
        #pragma unroll
        for(int m=0;m<8;m++){
            float4 bv = __ldg(bp4 + m*32 + lane);
            float4 a = oA[m]; a.x += bv.x; a.y += bv.y; a.z += bv.z; a.w += bv.w;
            float4 b = oB[m]; b.x += bv.x; b.y += bv.y; b.z += bv.z; b.w += bv.w;
            outA[m*32 + lane] = a;
            outB[m*32 + lane] = b;
        }
    }
}

extern "C" void kernel_launch(void* const* d_in, const int* in_sizes, int n_in,
                              void* d_out, int out_size)
{
    const float* h    = (const float*)d_in[0];   // [B,L,D]
    const float* mask = (const float*)d_in[1];   // [B,L]
    const float* Wp   = (const float*)d_in[2];   // [V,D]
    const float* bp   = (const float*)d_in[3];   // [V]
    const float* Wpi  = (const float*)d_in[4];   // [D,V]
    const float* bpi  = (const float*)d_in[5];   // [D]
    const float* emb  = (const float*)d_in[6];   // [K,V]
    float* out = (float*)d_out;
    long long osz = (long long)out_size;

    prep_kernel<<<768, 256>>>(emb, Wpi, Wp, out, osz);
    vq_main_kernel<<<NTOK/TPB, 256>>>(h, mask, bp, bpi, out, osz);
}

// round 17
// speedup vs baseline: 4.5576x; 1.1565x over previous
#include <cuda_runtime.h>

// Shapes (fixed by the problem)
#define BB   4
#define LL   2048
#define DD   1024
#define VV   32
#define KK   4096
#define NTOK (BB*LL)     // 8192 tokens
#define TPB  32          // tokens per block (= warp lanes; lane t owns token t)
#define NW   8           // warps per block (each owns a K-slice)
#define KW   (KK/NW)     // 512 codes per warp
#define CT   32          // codes per smem tile
#define NT2  (KW/CT)     // 16 tiles per warp

#define LOG2E 1.4426950408889634f

// Scratch (static device globals — no allocation)
__device__ float g_embn[KK*VV];    // normalized codebook
__device__ float g_ne2[KK];        // log2e*(sum(emb_n^2) + 1): shift+log2e folded
__device__ float g_wpiT[VV*DD];    // Wpi transposed: [v][d]
__device__ float g_wpT4[DD*VV];    // Wp interleaved: [(d/4)][v][d%4] -> coalesced float4

typedef unsigned long long ull;

__device__ __forceinline__ ull fma2(ull a, ull b, ull c){
    ull d;
    asm("fma.rn.f32x2 %0, %1, %2, %3;" : "=l"(d) : "l"(a), "l"(b), "l"(c));
    return d;
}
__device__ __forceinline__ ull add2(ull a, ull b){
    ull d;
    asm("add.rn.f32x2 %0, %1, %2;" : "=l"(d) : "l"(a), "l"(b));
    return d;
}
__device__ __forceinline__ ull pack2(float x, float y){
    ull r;
    asm("mov.b64 %0, {%1, %2};" : "=l"(r) : "f"(x), "f"(y));
    return r;
}
__device__ __forceinline__ float2 unpack2(ull a){
    float x, y;
    asm("mov.b64 {%0, %1}, %2;" : "=f"(x), "=f"(y) : "l"(a));
    return make_float2(x, y);
}
__device__ __forceinline__ float ex2(float x){
    float r;
    asm("ex2.approx.ftz.f32 %0, %1;" : "=f"(r) : "f"(x));
    return r;
}
__device__ __forceinline__ void cp16(void* dst, const void* src){
    unsigned s = (unsigned)__cvta_generic_to_shared(dst);
    asm volatile("cp.async.cg.shared.global [%0], [%1], 16;" :: "r"(s), "l"(src));
}
__device__ __forceinline__ void cp4(void* dst, const void* src){
    unsigned s = (unsigned)__cvta_generic_to_shared(dst);
    asm volatile("cp.async.ca.shared.global [%0], [%1], 4;" :: "r"(s), "l"(src));
}

// ---------------------------------------------------------------------------
// Merged prep kernel
// ---------------------------------------------------------------------------
__global__ void prep_kernel(const float* __restrict__ emb,
                            const float* __restrict__ Wpi,
                            const float* __restrict__ Wp,
                            float* __restrict__ out, long long out_size){
    int b = blockIdx.x;
    if(b < 512){
        int r = b * 8 + (threadIdx.x >> 5);
        int v = threadIdx.x & 31;
        float val = emb[r*VV + v];
        float ss = val * val;
        #pragma unroll
        for(int o=16;o;o>>=1) ss += __shfl_xor_sync(0xffffffffu, ss, o);
        float en = val * rsqrtf(ss);
        g_embn[r*VV + v] = en;
        float s2 = en * en;
        #pragma unroll
        for(int o=16;o;o>>=1) s2 += __shfl_xor_sync(0xffffffffu, s2, o);
        if(v == 0) g_ne2[r] = (s2 + 1.0f) * LOG2E;   // shift + log2e folded in
    } else if(b < 640){
        int i = (b - 512) * 256 + threadIdx.x;   // over D*V
        int d = i >> 5, v = i & 31;              // Wpi[d][v]
        g_wpiT[v*DD + d] = Wpi[i];
        if(i == 0){
            long long qn = (long long)NTOK * DD;
            if(out_size >= qn + NTOK + 1) out[qn + NTOK] = 0.0f;  // vq_loss
        }
    } else {
        int i = (b - 640) * 256 + threadIdx.x;   // over V*D (coalesced Wp read)
        int v = i >> 10, d = i & 1023;           // Wp[v][d]
        g_wpT4[(d >> 2)*128 + v*4 + (d & 3)] = Wp[i];
    }
}

// ---------------------------------------------------------------------------
// Main fused kernel: token-major lanes (R9 layout), K-sliced warps, occ-2,
// instruction-diet inner loop (ex2 folding, 2-chain score, fma2 everywhere)
// ---------------------------------------------------------------------------
__global__ void __launch_bounds__(256, 2)
vq_main_kernel(const float* __restrict__ h,
               const float* __restrict__ attn_mask,
               const float* __restrict__ bp,
               const float* __restrict__ bpi,
               float* __restrict__ out, long long out_size)
{
    __shared__ __align__(16) float s_e[NW][2][CT*VV];   // 64 KB (reused for partials)
    __shared__ __align__(16) float s_ne2[NW][2][CT];    // 2 KB
    __shared__ __align__(16) float s_hp[TPB*36];        // 4.6 KB (padded rows)
    __shared__ __align__(16) float4 s_comb[NW*TPB];     // 4 KB {l, best, idx, -}
    __shared__ __align__(16) float s_scale[TPB];
    __shared__ __align__(16) float s_q[TPB*VV];         // 4 KB

    const int tid  = threadIdx.x;
    const int w    = tid >> 5;        // 0..7 : K-slice id
    const int lane = tid & 31;        // token id within block
    const int blk  = blockIdx.x;
    const long long qn = (long long)NTOK * DD;

    // ---- prefetch this warp's tile 0 (overlaps phase 1) ----
    {
        const float* src = g_embn + (w*KW)*VV;
        #pragma unroll
        for(int r=0;r<8;r++){
            int i = lane + 32*r;      // 256 x 16B chunks = 4KB
            cp16(&s_e[w][0][i*4], src + i*4);
        }
        cp4(&s_ne2[w][0][lane], g_ne2 + w*KW + lane);
        asm volatile("cp.async.commit_group;");
    }

    // ---- phase 1: hp for 4 tokens per warp (lane = v index), fma2 path ----
    {
        const int tok0 = blk*TPB + 4*w;
        const ulonglong2* h0 = (const ulonglong2*)(h + (long long)(tok0  )*DD);
        const ulonglong2* h1 = (const ulonglong2*)(h + (long long)(tok0+1)*DD);
        const ulonglong2* h2 = (const ulonglong2*)(h + (long long)(tok0+2)*DD);
        const ulonglong2* h3 = (const ulonglong2*)(h + (long long)(tok0+3)*DD);
        const ulonglong2* wT = (const ulonglong2*)g_wpT4;
        ull a0=0ull,b0=0ull, a1=0ull,b1=0ull, a2=0ull,b2=0ull, a3=0ull,b3=0ull;
        #pragma unroll 4
        for(int g=0;g<DD/4;g++){
            ulonglong2 wv = wT[g*32 + lane];   // lane-consecutive LDG.128
            ulonglong2 x0 = h0[g];             // warp-uniform broadcast
            a0 = fma2(wv.x, x0.x, a0);  b0 = fma2(wv.y, x0.y, b0);
            ulonglong2 x1 = h1[g];
            a1 = fma2(wv.x, x1.x, a1);  b1 = fma2(wv.y, x1.y, b1);
            ulonglong2 x2 = h2[g];
            a2 = fma2(wv.x, x2.x, a2);  b2 = fma2(wv.y, x2.y, b2);
            ulonglong2 x3 = h3[g];
            a3 = fma2(wv.x, x3.x, a3);  b3 = fma2(wv.y, x3.y, b3);
        }
        float bpl = __ldg(bp + lane);
        float2 f0 = unpack2(add2(a0,b0));
        float2 f1 = unpack2(add2(a1,b1));
        float2 f2 = unpack2(add2(a2,b2));
        float2 f3 = unpack2(add2(a3,b3));
        float d0 = f0.x + f0.y + bpl;
        float d1 = f1.x + f1.y + bpl;
        float d2 = f2.x + f2.y + bpl;
        float d3 = f3.x + f3.y + bpl;
        float s0=d0*d0, s1=d1*d1, s2=d2*d2, s3=d3*d3;
        #pragma unroll
        for(int o=16;o;o>>=1){
            s0 += __shfl_xor_sync(0xffffffffu, s0, o);
            s1 += __shfl_xor_sync(0xffffffffu, s1, o);
            s2 += __shfl_xor_sync(0xffffffffu, s2, o);
            s3 += __shfl_xor_sync(0xffffffffu, s3, o);
        }
        // store 2*log2e*normalized hp so the dot is already in exp2 domain
        const float c = 2.0f * LOG2E;
        s_hp[(4*w  )*36 + lane] = d0 * (c * rsqrtf(s0));
        s_hp[(4*w+1)*36 + lane] = d1 * (c * rsqrtf(s1));
        s_hp[(4*w+2)*36 + lane] = d2 * (c * rsqrtf(s2));
        s_hp[(4*w+3)*36 + lane] = d3 * (c * rsqrtf(s3));
    }
    __syncthreads();

    // ---- each lane loads ITS token's hp into registers ----
    ull hp[16];
    {
        const ulonglong2* hr = (const ulonglong2*)&s_hp[lane*36];  // 144B rows, 16B aligned
        #pragma unroll
        for(int u=0;u<8;u++){ ulonglong2 x = hr[u]; hp[2*u] = x.x; hp[2*u+1] = x.y; }
    }

    // ---- main loop over this warp's K-slice (warp-private pipeline) ----
    ull acc[16];
    #pragma unroll
    for(int u=0;u<16;u++) acc[u] = 0ull;
    float l = 0.f, best = -1e30f;
    int   idx = 0;
    const int cbase = w*KW;

    for(int t2=0;t2<NT2;t2++){
        const int buf = t2 & 1;
        if(t2 + 1 < NT2){
            const float* src = g_embn + (cbase + (t2+1)*CT)*VV;
            #pragma unroll
            for(int r=0;r<8;r++){
                int i = lane + 32*r;
                cp16(&s_e[w][buf^1][i*4], src + i*4);
            }
            cp4(&s_ne2[w][buf^1][lane], g_ne2 + cbase + (t2+1)*CT + lane);
            asm volatile("cp.async.commit_group;");
            asm volatile("cp.async.wait_group 1;");
        } else {
            asm volatile("cp.async.wait_group 0;");
        }
        __syncwarp();

        const float* se = &s_e[w][buf][0];
        const int codebase = cbase + t2*CT;

        #pragma unroll 2
        for(int j=0;j<CT;j++){
            const ulonglong2* er = (const ulonglong2*)(se + j*VV);  // broadcast
            ull e[16];
            #pragma unroll
            for(int u=0;u<8;u++){ ulonglong2 x = er[u]; e[2*u] = x.x; e[2*u+1] = x.y; }

            // 2 independent chains, depth 8 (hidden by unroll-2 pipelining)
            ull c0 = 0ull, c1 = 0ull;
            #pragma unroll
            for(int u=0;u<8;u++){
                c0 = fma2(hp[u  ], e[u  ], c0);
                c1 = fma2(hp[8+u], e[8+u], c1);
            }
            float2 f = unpack2(add2(c0, c1));
            float sc = (f.x + f.y) - s_ne2[w][buf][j];   // log2e*(2s - ne2 - 1)
            if(sc > best){ best = sc; idx = codebase + j; }
            float p = ex2(sc);                           // = expf(orig score), <= ~1
            l += p;
            ull pp = pack2(p, p);
            #pragma unroll
            for(int u=0;u<16;u++) acc[u] = fma2(pp, e[u], acc[u]);
        }
    }

    // ---- write per-warp partials (overlay s_e; all warps done reading) ----
    __syncthreads();
    {
        float* prow = ((float*)s_e) + (w*TPB + lane)*36;   // padded rows
        ulonglong2* pr2 = (ulonglong2*)prow;
        #pragma unroll
        for(int u=0;u<8;u++){ ulonglong2 x; x.x = acc[2*u]; x.y = acc[2*u+1]; pr2[u] = x; }
        s_comb[w*TPB + lane] = make_float4(l, best, __int_as_float(idx), 0.f);
    }
    __syncthreads();

    // ---- cross-warp combine: 8 threads per token ----
    {
        const int t = tid >> 3, g = tid & 7;
        float4 sum = make_float4(0.f,0.f,0.f,0.f);
        #pragma unroll
        for(int ww=0;ww<NW;ww++){
            const float4* pr = (const float4*)(((float*)s_e) + (ww*TPB + t)*36);
            float4 v = pr[g];
            sum.x += v.x; sum.y += v.y; sum.z += v.z; sum.w += v.w;
        }
        if(g == 0){
            float lt = 0.f, bv = -1e30f; int bi = 0;
            #pragma unroll
            for(int ww=0;ww<NW;ww++){
                float4 c = s_comb[ww*TPB + t];
                lt += c.x;
                if(c.y > bv){ bv = c.y; bi = __float_as_int(c.z); }   // ascending slices: first max kept
            }
            float mk = (attn_mask[blk*TPB + t] == 1.0f) ? 1.0f : 0.0f;
            s_scale[t] = mk / lt;
            if(out_size >= qn + NTOK) out[qn + blk*TPB + t] = mk * (float)bi;
        }
        __syncthreads();
        float scl = s_scale[t];
        ((float4*)(s_q + t*VV))[g] = make_float4(sum.x*scl, sum.y*scl, sum.z*scl, sum.w*scl);
    }
    __syncthreads();

    // ---- epilogue: out = q @ Wpi^T + bpi; fma2 path; warp w -> tokens 4w..4w+3 ----
    #pragma unroll 1
    for(int ps=0; ps<2; ps++){
        const int tA = 4*w + 2*ps, tB = tA + 1;
        ull oA[16], oB[16];
        #pragma unroll
        for(int m=0;m<16;m++){ oA[m]=0ull; oB[m]=0ull; }
        #pragma unroll 2
        for(int v=0;v<VV;v++){
            ull qa = pack2(s_q[tA*VV + v], s_q[tA*VV + v]);   // smem broadcast
            ull qb = pack2(s_q[tB*VV + v], s_q[tB*VV + v]);
            const ulonglong2* wr = (const ulonglong2*)(g_wpiT + v*DD);
            #pragma unroll
            for(int m=0;m<8;m++){
                ulonglong2 wv = wr[m*32 + lane];   // d = 128*m + 4*lane, coalesced (L2-hot)
                oA[2*m  ] = fma2(qa, wv.x, oA[2*m  ]);
                oA[2*m+1] = fma2(qa, wv.y, oA[2*m+1]);
                oB[2*m  ] = fma2(qb, wv.x, oB[2*m  ]);
                oB[2*m+1] = fma2(qb, wv.y, oB[2*m+1]);
            }
        }
        float4* outA = (float4*)(out + (long long)(blk*TPB + tA) * DD);
        float4* outB = (float4*)(out + (long long)(blk*TPB + tB) * DD);
        const ulonglong2* bp4 = (const ulonglong2*)bpi;
        #pragma unroll
        for(int m=0;m<8;m++){
            ulonglong2 bv = bp4[m*32 + lane];
            ull ax = add2(oA[2*m], bv.x), ay = add2(oA[2*m+1], bv.y);
            ull bx = add2(oB[2*m], bv.x), by = add2(oB[2*m+1], bv.y);
            float2 axf = unpack2(ax), ayf = unpack2(ay);
            float2 bxf = unpack2(bx), byf = unpack2(by);
            outA[m*32 + lane] = make_float4(axf.x, axf.y, ayf.x, ayf.y);
            outB[m*32 + lane] = make_float4(bxf.x, bxf.y, byf.x, byf.y);
        }
    }
}

extern "C" void kernel_launch(void* const* d_in, const int* in_sizes, int n_in,
                              void* d_out, int out_size)
{
    const float* h    = (const float*)d_in[0];   // [B,L,D]
    const float* mask = (const float*)d_in[1];   // [B,L]
    const float* Wp   = (const float*)d_in[2];   // [V,D]
    const float* bp   = (const float*)d_in[3];   // [V]
    const float* Wpi  = (const float*)d_in[4];   // [D,V]
    const float* bpi  = (const float*)d_in[5];   // [D]
    const float* emb  = (const float*)d_in[6];   // [K,V]
    float* out = (float*)d_out;
    long long osz = (long long)out_size;

    prep_kernel<<<768, 256>>>(emb, Wpi, Wp, out, osz);
    vq_main_kernel<<<NTOK/TPB, 256>>>(h, mask, bp, bpi, out, osz);
}